// round 15
// baseline (speedup 1.0000x reference)
#include <cuda_runtime.h>
#include <math.h>

#define B_DIM 2048
#define T_DIM 256
#define IN_DIM 128
#define H_DIM 256
#define G3 768   // 3*H

typedef unsigned long long ull;

// Scratch (static device arrays)
__device__ float g_gi[(size_t)B_DIM * T_DIM * G3];   // [B][T][768], pre-biased
// Packed W: for k2 in [0,128), pair p in [0,384):
//   Wq[k2*1536 + p*4 + {0,1,2,3}] = Whh[2p][2k2], Whh[2p+1][2k2],
//                                   Whh[2p][2k2+1], Whh[2p+1][2k2+1]
__device__ float g_Wq[(size_t)(H_DIM / 2) * 2 * G3];

// ---------------------------------------------------------------------------
// Packed fp32x2 helpers. Each half is an independent IEEE fp32 FMA with
// single rounding -> bit-identical to scalar FFMA chains.
// ---------------------------------------------------------------------------
__device__ __forceinline__ ull dup2(float x) {
    ull r; asm("mov.b64 %0, {%1, %1};" : "=l"(r) : "f"(x)); return r;
}
__device__ __forceinline__ void ffma2(ull &d, ull a, ull b) {
    asm("fma.rn.f32x2 %0, %1, %2, %0;" : "+l"(d) : "l"(a), "l"(b));
}
__device__ __forceinline__ void unpack2(ull v, float &x, float &y) {
    asm("mov.b64 {%0, %1}, %2;" : "=f"(x), "=f"(y) : "l"(v));
}

// ---------------------------------------------------------------------------
// XLA f32 tanh (Eigen rational poly, FMA-contracted) — bit-exact vs reference
// ---------------------------------------------------------------------------
__device__ __forceinline__ float tanh_xla(float x) {
    const float kClamp = 7.90531110763549805f;
    float xc = fminf(fmaxf(x, -kClamp), kClamp);

    const float a1  = 4.89352455891786e-03f;
    const float a3  = 6.37261928875436e-04f;
    const float a5  = 1.48572235717979e-05f;
    const float a7  = 5.12229709037114e-08f;
    const float a9  = -8.60467152213735e-11f;
    const float a11 = 2.00018790482477e-13f;
    const float a13 = -2.76076847742355e-16f;
    const float b0  = 4.89352518554385e-03f;
    const float b2  = 2.26843463243900e-03f;
    const float b4  = 1.18534705686654e-04f;
    const float b6  = 1.19825839466702e-06f;

    float x2 = __fmul_rn(xc, xc);

    float p = a13;
    p = fmaf(x2, p, a11);
    p = fmaf(x2, p, a9);
    p = fmaf(x2, p, a7);
    p = fmaf(x2, p, a5);
    p = fmaf(x2, p, a3);
    p = fmaf(x2, p, a1);
    float num = __fmul_rn(xc, p);

    float q = b6;
    q = fmaf(x2, q, b4);
    q = fmaf(x2, q, b2);
    q = fmaf(x2, q, b0);

    float ratio = __fdiv_rn(num, q);
    return (fabsf(x) < 0.0004f) ? x : ratio;
}

__device__ __forceinline__ float sigmoid_xla(float x) {
    float t = tanh_xla(__fmul_rn(0.5f, x));
    return fmaf(0.5f, t, 0.5f);
}

// ---------------------------------------------------------------------------
// One-off W packer (see g_Wq layout comment)
// ---------------------------------------------------------------------------
__global__ void pack_wq(const float* __restrict__ Whh, float* __restrict__ Wq)
{
    int idx = blockIdx.x * blockDim.x + threadIdx.x;   // 0..196607
    int k2 = idx / 1536;
    int r  = idx - k2 * 1536;
    int p  = r >> 2;
    int j  = r & 3;
    int n  = 2 * p + (j & 1);
    int k  = 2 * k2 + (j >> 1);
    Wq[idx] = Whh[(size_t)n * H_DIM + k];
}

// Dummy kernels for deterministic ncu launch alignment (persist = launch #5)
__global__ void dummy_k() {}

// ---------------------------------------------------------------------------
// gi GEMM (r6-proven) + pre-biased store: C = fl( (X @ Wih^T) + b_ih ).
// Each output remains one serial ascending-k FMA chain, then one fadd —
// exactly the reference's gi + b_ih.
// ---------------------------------------------------------------------------
template<int K>
__global__ __launch_bounds__(128) void sgemm_nt2(
    const float* __restrict__ A, const float* __restrict__ W,
    const float* __restrict__ bias, float* __restrict__ C)
{
    __shared__ alignas(8) float As[16][66];
    __shared__ float Ws[16][66];

    const int tid = threadIdx.x;
    const int tn  = tid & 15;
    const int tm  = tid >> 4;
    const size_t m0 = (size_t)blockIdx.x * 64;
    const int    n0 = blockIdx.y * 64;

    const int lk = tid & 15;
    const int lm = tid >> 4;

    ull acc[4][4];
#pragma unroll
    for (int p = 0; p < 4; p++)
#pragma unroll
        for (int j = 0; j < 4; j++) acc[p][j] = 0ULL;

#pragma unroll 1
    for (int k0 = 0; k0 < K; k0 += 16) {
#pragma unroll
        for (int it = 0; it < 8; it++) {
            int m = lm + it * 8;
            As[lk][m] = A[(m0 + m) * K + (k0 + lk)];
            Ws[lk][m] = W[(size_t)(n0 + m) * K + (k0 + lk)];
        }
        __syncthreads();
#pragma unroll
        for (int kk = 0; kk < 16; kk++) {
            ull a[4];
#pragma unroll
            for (int p = 0; p < 4; p++)
                a[p] = *(const ull*)&As[kk][tm * 8 + 2 * p];
#pragma unroll
            for (int j = 0; j < 4; j++) {
                ull w2 = dup2(Ws[kk][tn * 4 + j]);
#pragma unroll
                for (int p = 0; p < 4; p++)
                    ffma2(acc[p][j], a[p], w2);
            }
        }
        __syncthreads();
    }

#pragma unroll
    for (int p = 0; p < 4; p++) {
        size_t r0 = m0 + tm * 8 + 2 * p;
#pragma unroll
        for (int j = 0; j < 4; j++) {
            float lo, hi;
            unpack2(acc[p][j], lo, hi);
            int col = n0 + tn * 4 + j;
            float b = bias[col];
            C[r0 * G3 + col]       = __fadd_rn(lo, b);
            C[(r0 + 1) * G3 + col] = __fadd_rn(hi, b);
        }
    }
}

// ---------------------------------------------------------------------------
// Persistent GRU: 256 blocks x 128 threads, 2 blocks/SM. Block owns MB=8
// batch rows for all 256 steps. Thread owns hc pair {2tid, 2tid+1} for ALL
// 8 rows -> every W address read once per block per step (multiplicity 1).
// W (LDG.128) and h (broadcast LDS.128) both register-double-buffered.
// ---------------------------------------------------------------------------
#define MB 8
#define HD_STRIDE 10                          // ulls per h k-row (16B aligned)
#define SM_H_ULLS (H_DIM * HD_STRIDE)         // 2560
#define SM_GI_FLOATS (MB * G3)                // 6144
#define SM_TOTAL_BYTES (SM_H_ULLS * 8 + SM_GI_FLOATS * 4)   // 45056

__device__ __forceinline__ void comp_kk(
    ull (&a0)[8], ull (&a1)[8], ull (&a2)[8],
    const ull* h, ull wr, ull wz, ull wn)
{
#pragma unroll
    for (int r = 0; r < 8; r++) {
        ffma2(a0[r], h[r], wr);
        ffma2(a1[r], h[r], wz);
        ffma2(a2[r], h[r], wn);
    }
}

#define LDW(Wb, k2p) do {                                                  \
    Wb[0] = *(const longlong2*)(wq_r + (size_t)(k2p) * 1536);              \
    Wb[1] = *(const longlong2*)(wq_z + (size_t)(k2p) * 1536);              \
    Wb[2] = *(const longlong2*)(wq_n + (size_t)(k2p) * 1536); } while (0)

#define LDH(Hb, k2p) do {                                                  \
    const ull* r0_ = h_dup + (size_t)(2 * (k2p)) * HD_STRIDE;              \
    const ull* r1_ = h_dup + (size_t)(2 * (k2p) + 1) * HD_STRIDE;          \
    *(ulonglong2*)&Hb[0]  = *(const ulonglong2*)(r0_ + 0);                 \
    *(ulonglong2*)&Hb[2]  = *(const ulonglong2*)(r0_ + 2);                 \
    *(ulonglong2*)&Hb[4]  = *(const ulonglong2*)(r0_ + 4);                 \
    *(ulonglong2*)&Hb[6]  = *(const ulonglong2*)(r0_ + 6);                 \
    *(ulonglong2*)&Hb[8]  = *(const ulonglong2*)(r1_ + 0);                 \
    *(ulonglong2*)&Hb[10] = *(const ulonglong2*)(r1_ + 2);                 \
    *(ulonglong2*)&Hb[12] = *(const ulonglong2*)(r1_ + 4);                 \
    *(ulonglong2*)&Hb[14] = *(const ulonglong2*)(r1_ + 6); } while (0)

#define COMP(Wb, Hb) do {                                                  \
    comp_kk(acc0, acc1, acc2, &Hb[0], (ull)Wb[0].x, (ull)Wb[1].x, (ull)Wb[2].x); \
    comp_kk(acc0, acc1, acc2, &Hb[8], (ull)Wb[0].y, (ull)Wb[1].y, (ull)Wb[2].y); } while (0)

__global__ __launch_bounds__(128, 2) void gru_persist(
    const float* __restrict__ gi_all,   // [B][T][768], pre-biased
    const float* __restrict__ Wq,       // packed
    const float* __restrict__ b_hh,
    float* __restrict__ out)            // [B][256]
{
    extern __shared__ ull sm[];
    ull*   h_dup = sm;                         // [256][HD_STRIDE] (h,h) pairs
    float* gi_sm = (float*)(sm + SM_H_ULLS);   // [8][768]

    const int tid = threadIdx.x;        // 0..127 -> hc pair {2tid, 2tid+1}
    const int hc0 = 2 * tid;
    const int m0  = blockIdx.x * MB;

    // zero h tile
#pragma unroll
    for (int i = 0; i < SM_H_ULLS / 128; i++) h_dup[tid + i * 128] = 0ULL;

    float bhr[2], bhz[2], bhn[2];
#pragma unroll
    for (int w = 0; w < 2; w++) {
        int hc = hc0 + w;
        bhr[w] = b_hh[hc]; bhz[w] = b_hh[hc + H_DIM]; bhn[w] = b_hh[hc + 2 * H_DIM];
    }

    float hprev[8][2];
#pragma unroll
    for (int r = 0; r < 8; r++) { hprev[r][0] = 0.0f; hprev[r][1] = 0.0f; }

    const float* wq_r = Wq + (size_t)(0 * 128 + tid) * 4;
    const float* wq_z = Wq + (size_t)(1 * 128 + tid) * 4;
    const float* wq_n = Wq + (size_t)(2 * 128 + tid) * 4;

    __syncthreads();

    for (int t = 0; t < T_DIM; t++) {
        // ---- prefetch this step's gi tile (8 x 768 = 24KB) via cp.async ----
#pragma unroll
        for (int i = 0; i < 12; i++) {
            int c  = tid + i * 128;          // 0..1535 16B chunks
            int mm = c / 192;
            int j  = c - mm * 192;
            const float* src = gi_all + ((size_t)(m0 + mm) * T_DIM + t) * G3 + j * 4;
            float* dst = gi_sm + mm * G3 + j * 4;
            unsigned daddr = (unsigned)__cvta_generic_to_shared(dst);
            asm volatile("cp.async.ca.shared.global [%0], [%1], 16;"
                         :: "r"(daddr), "l"(src) : "memory");
        }
        asm volatile("cp.async.commit_group;" ::: "memory");

        // ---- recurrent GEMM: double-buffered W (LDG) and h (LDS) ----
        ull acc0[8], acc1[8], acc2[8];
#pragma unroll
        for (int r = 0; r < 8; r++) { acc0[r] = 0ULL; acc1[r] = 0ULL; acc2[r] = 0ULL; }

        longlong2 wA[3], wB[3];
        ull hA[16], hB[16];

        LDW(wA, 0); LDH(hA, 0);
#pragma unroll 1
        for (int k2 = 0; k2 < 126; k2 += 2) {
            LDW(wB, k2 + 1); LDH(hB, k2 + 1);
            COMP(wA, hA);                       // k2
            LDW(wA, k2 + 2); LDH(hA, k2 + 2);
            COMP(wB, hB);                       // k2 + 1
        }
        LDW(wB, 127); LDH(hB, 127);
        COMP(wA, hA);                           // 126
        COMP(wB, hB);                           // 127

        asm volatile("cp.async.wait_group 0;" ::: "memory");
        __syncthreads();   // gi ready; all h_dup reads of this step done

        // ---- epilogue: exact XLA combine + sign (bit-exact, unchanged) ----
#pragma unroll
        for (int r = 0; r < 8; r++) {
            float gr2[2], gz2[2], gn2[2];
            unpack2(acc0[r], gr2[0], gr2[1]);
            unpack2(acc1[r], gz2[0], gz2[1]);
            unpack2(acc2[r], gn2[0], gn2[1]);
            const float* gi = gi_sm + r * G3;
#pragma unroll
            for (int hw = 0; hw < 2; hw++) {
                const int hc = hc0 + hw;

                float i_r = gi[hc];              // pre-biased in phase 1
                float i_z = gi[hc +     H_DIM];
                float i_n = gi[hc + 2 * H_DIM];
                float h_r = __fadd_rn(gr2[hw], bhr[hw]);
                float h_z = __fadd_rn(gz2[hw], bhz[hw]);
                float h_n = __fadd_rn(gn2[hw], bhn[hw]);

                float rg = sigmoid_xla(__fadd_rn(i_r, h_r));
                float zg = sigmoid_xla(__fadd_rn(i_z, h_z));
                float ng = tanh_xla(fmaf(rg, h_n, i_n));

                float omz  = __fsub_rn(1.0f, zg);
                float zh   = __fmul_rn(zg, hprev[r][hw]);
                float hnew = fmaf(omz, ng, zh);

                float s = (hnew > 0.0f) ? 1.0f : ((hnew < 0.0f) ? -1.0f : 0.0f);
                hprev[r][hw] = s;

                h_dup[(size_t)hc * HD_STRIDE + r] = dup2(s);

                if (t == T_DIM - 1)
                    out[(size_t)(m0 + r) * H_DIM + hc] = s;
            }
        }

        __syncthreads();   // new h visible before next step's GEMM
    }
}

extern "C" void kernel_launch(void* const* d_in, const int* in_sizes, int n_in,
                              void* d_out, int out_size)
{
    const float* x   = (const float*)d_in[0];  // [2048, 256, 128]
    const float* Wih = (const float*)d_in[1];  // [768, 128]
    const float* Whh = (const float*)d_in[2];  // [768, 256]
    const float* bih = (const float*)d_in[3];  // [768]
    const float* bhh = (const float*)d_in[4];  // [768]
    float* out = (float*)d_out;                // [2048, 256]

    float *gi_p, *wq_p;
    cudaGetSymbolAddress((void**)&gi_p, g_gi);
    cudaGetSymbolAddress((void**)&wq_p, g_Wq);

    cudaFuncSetAttribute(gru_persist, cudaFuncAttributeMaxDynamicSharedMemorySize,
                         SM_TOTAL_BYTES);

    // Launch #0: pack Whh into the LDG.128-friendly layout.
    pack_wq<<<(H_DIM / 2 * 2 * G3) / 256, 256>>>(Whh, wq_p);

    // Launch #1: gi = fl(X @ W_ih^T + b_ih)  -> [B][T][768]
    {
        dim3 grid((B_DIM * T_DIM) / 64, G3 / 64);
        sgemm_nt2<IN_DIM><<<grid, 128>>>(x, Wih, bih, gi_p);
    }

    // Launches #2-#4: alignment dummies so ncu (-s 5 -c 1) captures persist.
    dummy_k<<<1, 32>>>();
    dummy_k<<<1, 32>>>();
    dummy_k<<<1, 32>>>();

    // Launch #5: persistent recurrence — one kernel for all 256 steps.
    gru_persist<<<B_DIM / MB, 128, SM_TOTAL_BYTES>>>(gi_p, wq_p, bhh, out);
}

// round 16
// speedup vs baseline: 1.5831x; 1.5831x over previous
#include <cuda_runtime.h>
#include <math.h>

#define B_DIM 2048
#define T_DIM 256
#define IN_DIM 128
#define H_DIM 256
#define G3 768   // 3*H

typedef unsigned long long ull;

// Scratch (static device arrays)
__device__ float g_gi[(size_t)B_DIM * T_DIM * G3];   // [B][T][768], pre-biased
// Packed W: for k2 in [0,128), pair p in [0,384):
//   Wq[k2*1536 + p*4 + {0,1,2,3}] = Whh[2p][2k2], Whh[2p+1][2k2],
//                                   Whh[2p][2k2+1], Whh[2p+1][2k2+1]
__device__ float g_Wq[(size_t)(H_DIM / 2) * 2 * G3];

// ---------------------------------------------------------------------------
// Packed fp32x2 helpers. Each half is an independent IEEE fp32 FMA with
// single rounding -> bit-identical to scalar FFMA chains.
// ---------------------------------------------------------------------------
__device__ __forceinline__ ull dup2(float x) {
    ull r; asm("mov.b64 %0, {%1, %1};" : "=l"(r) : "f"(x)); return r;
}
__device__ __forceinline__ void ffma2(ull &d, ull a, ull b) {
    asm("fma.rn.f32x2 %0, %1, %2, %0;" : "+l"(d) : "l"(a), "l"(b));
}
__device__ __forceinline__ void unpack2(ull v, float &x, float &y) {
    asm("mov.b64 {%0, %1}, %2;" : "=f"(x), "=f"(y) : "l"(v));
}

// ---------------------------------------------------------------------------
// XLA f32 tanh (Eigen rational poly, FMA-contracted) — bit-exact vs reference
// ---------------------------------------------------------------------------
__device__ __forceinline__ float tanh_xla(float x) {
    const float kClamp = 7.90531110763549805f;
    float xc = fminf(fmaxf(x, -kClamp), kClamp);

    const float a1  = 4.89352455891786e-03f;
    const float a3  = 6.37261928875436e-04f;
    const float a5  = 1.48572235717979e-05f;
    const float a7  = 5.12229709037114e-08f;
    const float a9  = -8.60467152213735e-11f;
    const float a11 = 2.00018790482477e-13f;
    const float a13 = -2.76076847742355e-16f;
    const float b0  = 4.89352518554385e-03f;
    const float b2  = 2.26843463243900e-03f;
    const float b4  = 1.18534705686654e-04f;
    const float b6  = 1.19825839466702e-06f;

    float x2 = __fmul_rn(xc, xc);

    float p = a13;
    p = fmaf(x2, p, a11);
    p = fmaf(x2, p, a9);
    p = fmaf(x2, p, a7);
    p = fmaf(x2, p, a5);
    p = fmaf(x2, p, a3);
    p = fmaf(x2, p, a1);
    float num = __fmul_rn(xc, p);

    float q = b6;
    q = fmaf(x2, q, b4);
    q = fmaf(x2, q, b2);
    q = fmaf(x2, q, b0);

    float ratio = __fdiv_rn(num, q);
    return (fabsf(x) < 0.0004f) ? x : ratio;
}

__device__ __forceinline__ float sigmoid_xla(float x) {
    float t = tanh_xla(__fmul_rn(0.5f, x));
    return fmaf(0.5f, t, 0.5f);
}

// ---------------------------------------------------------------------------
// One-off W packer (see g_Wq layout comment)
// ---------------------------------------------------------------------------
__global__ void pack_wq(const float* __restrict__ Whh, float* __restrict__ Wq)
{
    int idx = blockIdx.x * blockDim.x + threadIdx.x;   // 0..196607
    int k2 = idx / 1536;
    int r  = idx - k2 * 1536;
    int p  = r >> 2;
    int j  = r & 3;
    int n  = 2 * p + (j & 1);
    int k  = 2 * k2 + (j >> 1);
    Wq[idx] = Whh[(size_t)n * H_DIM + k];
}

// ---------------------------------------------------------------------------
// gi GEMM (r6-proven) + pre-biased store: C = fl( (X @ Wih^T) + b_ih ).
// ---------------------------------------------------------------------------
template<int K>
__global__ __launch_bounds__(128) void sgemm_nt2(
    const float* __restrict__ A, const float* __restrict__ W,
    const float* __restrict__ bias, float* __restrict__ C)
{
    __shared__ alignas(8) float As[16][66];
    __shared__ float Ws[16][66];

    const int tid = threadIdx.x;
    const int tn  = tid & 15;
    const int tm  = tid >> 4;
    const size_t m0 = (size_t)blockIdx.x * 64;
    const int    n0 = blockIdx.y * 64;

    const int lk = tid & 15;
    const int lm = tid >> 4;

    ull acc[4][4];
#pragma unroll
    for (int p = 0; p < 4; p++)
#pragma unroll
        for (int j = 0; j < 4; j++) acc[p][j] = 0ULL;

#pragma unroll 1
    for (int k0 = 0; k0 < K; k0 += 16) {
#pragma unroll
        for (int it = 0; it < 8; it++) {
            int m = lm + it * 8;
            As[lk][m] = A[(m0 + m) * K + (k0 + lk)];
            Ws[lk][m] = W[(size_t)(n0 + m) * K + (k0 + lk)];
        }
        __syncthreads();
#pragma unroll
        for (int kk = 0; kk < 16; kk++) {
            ull a[4];
#pragma unroll
            for (int p = 0; p < 4; p++)
                a[p] = *(const ull*)&As[kk][tm * 8 + 2 * p];
#pragma unroll
            for (int j = 0; j < 4; j++) {
                ull w2 = dup2(Ws[kk][tn * 4 + j]);
#pragma unroll
                for (int p = 0; p < 4; p++)
                    ffma2(acc[p][j], a[p], w2);
            }
        }
        __syncthreads();
    }

#pragma unroll
    for (int p = 0; p < 4; p++) {
        size_t r0 = m0 + tm * 8 + 2 * p;
#pragma unroll
        for (int j = 0; j < 4; j++) {
            float lo, hi;
            unpack2(acc[p][j], lo, hi);
            int col = n0 + tn * 4 + j;
            float b = bias[col];
            C[r0 * G3 + col]       = __fadd_rn(lo, b);
            C[(r0 + 1) * G3 + col] = __fadd_rn(hi, b);
        }
    }
}

// ---------------------------------------------------------------------------
// Persistent GRU (r13-proven geometry): 256 blocks x 256 threads, 2 blocks/SM.
// Block owns MB=8 batch rows for all 256 steps; thread tile = 1 hc-pair x 4
// rows x 3 gates. Single change vs r13: 4-deep rolling W register pipeline
// so each W LDG has ~3 k2 iterations of FMA before first consumption.
// ---------------------------------------------------------------------------
#define MB 8
#define HD_STRIDE 10                          // ulls per h k-row (16B aligned)
#define SM_H_ULLS (H_DIM * HD_STRIDE)         // 2560
#define SM_GI_FLOATS (MB * G3)                // 6144
#define SM_TOTAL_BYTES (SM_H_ULLS * 8 + SM_GI_FLOATS * 4)   // 45056

#define LDW(Wb, k2p) do {                                                  \
    Wb[0] = *(const longlong2*)(wq_r + (size_t)(k2p) * 1536);              \
    Wb[1] = *(const longlong2*)(wq_z + (size_t)(k2p) * 1536);              \
    Wb[2] = *(const longlong2*)(wq_n + (size_t)(k2p) * 1536); } while (0)

// Consume buffer Wb for k2 = k2v: both kk halves, ascending, h loaded inline.
#define COMPH(Wb, k2v) do {                                                \
    const ulonglong2* h0_ =                                                \
        (const ulonglong2*)(h_dup + (size_t)(2 * (k2v)) * HD_STRIDE + mg4);\
    const ulonglong2* h1_ =                                                \
        (const ulonglong2*)(h_dup + (size_t)(2 * (k2v) + 1) * HD_STRIDE + mg4);\
    ulonglong2 p0_ = h0_[0], p1_ = h0_[1];                                 \
    ffma2(acc[0][0], p0_.x, (ull)Wb[0].x); ffma2(acc[1][0], p0_.x, (ull)Wb[1].x); ffma2(acc[2][0], p0_.x, (ull)Wb[2].x); \
    ffma2(acc[0][1], p0_.y, (ull)Wb[0].x); ffma2(acc[1][1], p0_.y, (ull)Wb[1].x); ffma2(acc[2][1], p0_.y, (ull)Wb[2].x); \
    ffma2(acc[0][2], p1_.x, (ull)Wb[0].x); ffma2(acc[1][2], p1_.x, (ull)Wb[1].x); ffma2(acc[2][2], p1_.x, (ull)Wb[2].x); \
    ffma2(acc[0][3], p1_.y, (ull)Wb[0].x); ffma2(acc[1][3], p1_.y, (ull)Wb[1].x); ffma2(acc[2][3], p1_.y, (ull)Wb[2].x); \
    p0_ = h1_[0]; p1_ = h1_[1];                                            \
    ffma2(acc[0][0], p0_.x, (ull)Wb[0].y); ffma2(acc[1][0], p0_.x, (ull)Wb[1].y); ffma2(acc[2][0], p0_.x, (ull)Wb[2].y); \
    ffma2(acc[0][1], p0_.y, (ull)Wb[0].y); ffma2(acc[1][1], p0_.y, (ull)Wb[1].y); ffma2(acc[2][1], p0_.y, (ull)Wb[2].y); \
    ffma2(acc[0][2], p1_.x, (ull)Wb[0].y); ffma2(acc[1][2], p1_.x, (ull)Wb[1].y); ffma2(acc[2][2], p1_.x, (ull)Wb[2].y); \
    ffma2(acc[0][3], p1_.y, (ull)Wb[0].y); ffma2(acc[1][3], p1_.y, (ull)Wb[1].y); ffma2(acc[2][3], p1_.y, (ull)Wb[2].y); \
} while (0)

__global__ __launch_bounds__(256, 2) void gru_persist(
    const float* __restrict__ gi_all,   // [B][T][768], pre-biased
    const float* __restrict__ Wq,       // packed
    const float* __restrict__ b_hh,
    float* __restrict__ out)            // [B][256]
{
    extern __shared__ ull sm[];
    ull*   h_dup = sm;                         // [256][HD_STRIDE] (h,h) pairs
    float* gi_sm = (float*)(sm + SM_H_ULLS);   // [8][768]

    const int tid = threadIdx.x;
    const int tn  = tid & 127;          // hc pair index: hc0 = 2*tn
    const int mg  = tid >> 7;           // 0/1 -> rows mg*4 .. mg*4+3
    const int hc0 = 2 * tn;
    const int mg4 = mg * 4;
    const int m0  = blockIdx.x * MB;

    // zero h tile
    for (int i = tid; i < SM_H_ULLS; i += 256) h_dup[i] = 0ULL;

    float bhr[2], bhz[2], bhn[2];
#pragma unroll
    for (int w = 0; w < 2; w++) {
        int hc = hc0 + w;
        bhr[w] = b_hh[hc]; bhz[w] = b_hh[hc + H_DIM]; bhn[w] = b_hh[hc + 2 * H_DIM];
    }

    float hprev[4][2];                  // [row][hw]
#pragma unroll
    for (int r = 0; r < 4; r++) { hprev[r][0] = 0.0f; hprev[r][1] = 0.0f; }

    const float* wq_r = Wq + (size_t)(0 * 128 + tn) * 4;
    const float* wq_z = Wq + (size_t)(1 * 128 + tn) * 4;
    const float* wq_n = Wq + (size_t)(2 * 128 + tn) * 4;

    __syncthreads();

    for (int t = 0; t < T_DIM; t++) {
        // ---- prefetch this step's gi tile (8 x 768 = 24KB) via cp.async ----
#pragma unroll
        for (int i = 0; i < 6; i++) {
            int c  = tid + i * 256;          // 0..1535 16B chunks
            int mm = c / 192;
            int j  = c - mm * 192;
            const float* src = gi_all + ((size_t)(m0 + mm) * T_DIM + t) * G3 + j * 4;
            float* dst = gi_sm + mm * G3 + j * 4;
            unsigned daddr = (unsigned)__cvta_generic_to_shared(dst);
            asm volatile("cp.async.ca.shared.global [%0], [%1], 16;"
                         :: "r"(daddr), "l"(src) : "memory");
        }
        asm volatile("cp.async.commit_group;" ::: "memory");

        // ---- recurrent GEMM: 4-deep rolling W pipeline, serial ascending k --
        ull acc[3][4];   // [gate][row]
#pragma unroll
        for (int g = 0; g < 3; g++)
#pragma unroll
            for (int r = 0; r < 4; r++) acc[g][r] = 0ULL;

        longlong2 w0[3], w1[3], w2[3], w3[3];
        LDW(w0, 0); LDW(w1, 1); LDW(w2, 2); LDW(w3, 3);

#pragma unroll 1
        for (int k2 = 0; k2 < 120; k2 += 4) {
            COMPH(w0, k2 + 0); LDW(w0, k2 + 4);
            COMPH(w1, k2 + 1); LDW(w1, k2 + 5);
            COMPH(w2, k2 + 2); LDW(w2, k2 + 6);
            COMPH(w3, k2 + 3); LDW(w3, k2 + 7);
        }
        // k2 = 120..123: refill for 124..127
        COMPH(w0, 120); LDW(w0, 124);
        COMPH(w1, 121); LDW(w1, 125);
        COMPH(w2, 122); LDW(w2, 126);
        COMPH(w3, 123); LDW(w3, 127);
        // k2 = 124..127: drain
        COMPH(w0, 124);
        COMPH(w1, 125);
        COMPH(w2, 126);
        COMPH(w3, 127);

        asm volatile("cp.async.wait_group 0;" ::: "memory");
        __syncthreads();   // gi ready; all h_dup reads of this step done

        // ---- epilogue: exact XLA combine + sign (bit-exact, unchanged) ----
#pragma unroll
        for (int r = 0; r < 4; r++) {
            float gr2[2], gz2[2], gn2[2];
            unpack2(acc[0][r], gr2[0], gr2[1]);
            unpack2(acc[1][r], gz2[0], gz2[1]);
            unpack2(acc[2][r], gn2[0], gn2[1]);
            const float* gi = gi_sm + (mg4 + r) * G3;
#pragma unroll
            for (int hw = 0; hw < 2; hw++) {
                const int hc = hc0 + hw;

                float i_r = gi[hc];              // pre-biased in phase 1
                float i_z = gi[hc +     H_DIM];
                float i_n = gi[hc + 2 * H_DIM];
                float h_r = __fadd_rn(gr2[hw], bhr[hw]);
                float h_z = __fadd_rn(gz2[hw], bhz[hw]);
                float h_n = __fadd_rn(gn2[hw], bhn[hw]);

                float rg = sigmoid_xla(__fadd_rn(i_r, h_r));
                float zg = sigmoid_xla(__fadd_rn(i_z, h_z));
                float ng = tanh_xla(fmaf(rg, h_n, i_n));

                float omz  = __fsub_rn(1.0f, zg);
                float zh   = __fmul_rn(zg, hprev[r][hw]);
                float hnew = fmaf(omz, ng, zh);

                float s = (hnew > 0.0f) ? 1.0f : ((hnew < 0.0f) ? -1.0f : 0.0f);
                hprev[r][hw] = s;

                h_dup[(size_t)hc * HD_STRIDE + mg4 + r] = dup2(s);

                if (t == T_DIM - 1)
                    out[(size_t)(m0 + mg4 + r) * H_DIM + hc] = s;
            }
        }

        __syncthreads();   // new h visible before next step's GEMM
    }
}

extern "C" void kernel_launch(void* const* d_in, const int* in_sizes, int n_in,
                              void* d_out, int out_size)
{
    const float* x   = (const float*)d_in[0];  // [2048, 256, 128]
    const float* Wih = (const float*)d_in[1];  // [768, 128]
    const float* Whh = (const float*)d_in[2];  // [768, 256]
    const float* bih = (const float*)d_in[3];  // [768]
    const float* bhh = (const float*)d_in[4];  // [768]
    float* out = (float*)d_out;                // [2048, 256]

    float *gi_p, *wq_p;
    cudaGetSymbolAddress((void**)&gi_p, g_gi);
    cudaGetSymbolAddress((void**)&wq_p, g_Wq);

    cudaFuncSetAttribute(gru_persist, cudaFuncAttributeMaxDynamicSharedMemorySize,
                         SM_TOTAL_BYTES);

    // Launch #0: pack Whh into the LDG.128-friendly layout.
    pack_wq<<<(H_DIM / 2 * 2 * G3) / 256, 256>>>(Whh, wq_p);

    // Launch #1: gi = fl(X @ W_ih^T + b_ih)  -> [B][T][768]
    {
        dim3 grid((B_DIM * T_DIM) / 64, G3 / 64);
        sgemm_nt2<IN_DIM><<<grid, 128>>>(x, Wih, bih, gi_p);
    }

    // Launch #2: persistent recurrence — one kernel for all 256 steps.
    gru_persist<<<B_DIM / MB, 256, SM_TOTAL_BYTES>>>(gi_p, wq_p, bhh, out);
}